// round 15
// baseline (speedup 1.0000x reference)
#include <cuda_runtime.h>
#include <cuda.h>
#include <cuda_bf16.h>
#include <cstdint>
#include <math.h>

// Problem constants
#define BB   64
#define NN   257
#define DD   1024
#define HH   16
#define HD   64
#define MROWS (BB*NN)          // 16448
#define KDIM 1024
#define NP   264               // padded key stride for V^T

// exp2-domain softmax constants (uniform shift cancels in normalization)
#define SC_LOG2   0.1803368801111137f    // 0.125 * log2(e)
#define SH_LOG2  -17.312340490667562f    // -12 * log2(e)

// GEMM tiling (TMA + mma.sync bf16 path, proven round 8)
#define BM 128
#define BN 128
#define BK 32
#define NITER (KDIM/BK)        // 32
#define GSTAGE 32768
#define GEMM_SMEM (3*GSTAGE)   // 98304 -> 2 CTAs/SM

// Attention (cp.async, proven R8 smem layout; FA2 register-P warp tiling)
#define AT_ROWB 144
#define AT_QH 0
#define AT_QM 18432
#define AT_KH 36864
#define AT_KM 46080
#define AT_VH 55296
#define AT_VM 64512
#define AT_PH 73728            // now only used as fbuf scratch for key-256
#define AT_MSK 110592
#define AT_SMEM 112896

// Scratch (device globals — no allocation allowed; zero-initialized)
__device__ int g_mask_mode;
__device__ __nv_bfloat16 g_xh[(size_t)MROWS * DD], g_xm[(size_t)MROWS * DD];
__device__ __nv_bfloat16 g_ah[(size_t)MROWS * DD], g_am[(size_t)MROWS * DD];
__device__ __nv_bfloat16 g_wh[3 * DD * DD],        g_wm[3 * DD * DD];
__device__ __nv_bfloat16 g_oh[DD * DD],            g_om[DD * DD];
__device__ __nv_bfloat16 g_qh[(size_t)BB*HH*NN*HD], g_qm[(size_t)BB*HH*NN*HD];
__device__ __nv_bfloat16 g_kh[(size_t)BB*HH*NN*HD], g_km[(size_t)BB*HH*NN*HD];
__device__ __nv_bfloat16 g_vh[(size_t)BB*HH*HD*NP], g_vm[(size_t)BB*HH*HD*NP];

// ---------------------------------------------------------------------------
// PTX helpers
// ---------------------------------------------------------------------------
__device__ __forceinline__ uint32_t smem_u32(const void* p) {
    uint32_t a;
    asm("{ .reg .u64 t; cvta.to.shared.u64 t, %1; cvt.u32.u64 %0, t; }"
        : "=r"(a) : "l"(p));
    return a;
}
__device__ __forceinline__ float ex2(float x) {
    float r;
    asm("ex2.approx.f32 %0, %1;" : "=f"(r) : "f"(x));
    return r;
}
__device__ __forceinline__ void cp16(uint32_t dst, const void* src, bool pred) {
    int sz = pred ? 16 : 0;
    asm volatile("cp.async.cg.shared.global [%0], [%1], 16, %2;"
                 :: "r"(dst), "l"(src), "r"(sz));
}
#define CP_COMMIT() asm volatile("cp.async.commit_group;")
#define CP_WAIT(n)  asm volatile("cp.async.wait_group %0;" :: "n"(n))

__device__ __forceinline__ void mbar_init(uint32_t a, uint32_t cnt) {
    asm volatile("mbarrier.init.shared.b64 [%0], %1;" :: "r"(a), "r"(cnt) : "memory");
}
__device__ __forceinline__ void mbar_expect(uint32_t a, uint32_t bytes) {
    asm volatile("mbarrier.arrive.expect_tx.shared.b64 _, [%0], %1;"
                 :: "r"(a), "r"(bytes) : "memory");
}
__device__ __forceinline__ void mbar_wait(uint32_t a, uint32_t ph) {
    asm volatile(
        "{\n\t.reg .pred P;\n"
        "WLOOP%=:\n\t"
        "mbarrier.try_wait.parity.acquire.cta.shared::cta.b64 P, [%0], %1, 0x989680;\n\t"
        "@!P bra WLOOP%=;\n\t}"
        :: "r"(a), "r"(ph) : "memory");
}
__device__ __forceinline__ void tma2d(uint32_t dst, const CUtensorMap* m,
                                      int cx, int cy, uint32_t mbar) {
    asm volatile(
        "cp.async.bulk.tensor.2d.shared::cta.global.tile.mbarrier::complete_tx::bytes "
        "[%0], [%1, {%2, %3}], [%4];"
        :: "r"(dst), "l"(m), "r"(cx), "r"(cy), "r"(mbar) : "memory");
}

#define LDM4(r, addr) \
    asm volatile("ldmatrix.sync.aligned.m8n8.x4.shared.b16 {%0,%1,%2,%3}, [%4];" \
        : "=r"((r)[0]), "=r"((r)[1]), "=r"((r)[2]), "=r"((r)[3]) : "r"(addr))

#define MMA(c, a, b0, b1) \
    asm volatile("mma.sync.aligned.m16n8k16.row.col.f32.bf16.bf16.f32 " \
        "{%0,%1,%2,%3}, {%4,%5,%6,%7}, {%8,%9}, {%0,%1,%2,%3};" \
        : "+f"((c)[0]), "+f"((c)[1]), "+f"((c)[2]), "+f"((c)[3]) \
        : "r"((a)[0]), "r"((a)[1]), "r"((a)[2]), "r"((a)[3]), "r"(b0), "r"(b1))

__device__ __forceinline__ void split2(float x, float y,
                                       __nv_bfloat162* hi, __nv_bfloat162* mid) {
    __nv_bfloat162 h = __float22bfloat162_rn(make_float2(x, y));
    float2 hf = __bfloat1622float2(h);
    *hi = h;
    *mid = __float22bfloat162_rn(make_float2(x - hf.x, y - hf.y));
}

// ---------------------------------------------------------------------------
// Mask dtype detector (proven)
// ---------------------------------------------------------------------------
__global__ void detect_mask_kernel(const unsigned char* __restrict__ p) {
    if (threadIdx.x != 0 || blockIdx.x != 0) return;
    bool bf16 = false, f32 = false, u8 = false;
    for (int i = 0; i < 1024; i++) {
        unsigned char v = p[i];
        if (v == 0x3F) {
            if ((i & 3) == 1) bf16 = true; else f32 = true;
        } else if (v == 1 && (i & 3) != 0) {
            u8 = true;
        }
    }
    g_mask_mode = bf16 ? 3 : (f32 ? 2 : (u8 ? 0 : 1));
}

__device__ __forceinline__ bool mask_at(const unsigned char* mask_raw,
                                        int mode, int idx) {
    if (mode == 0) return mask_raw[idx] != 0;
    if (mode == 1) return ((const int*)mask_raw)[idx] != 0;
    if (mode == 2) return ((const float*)mask_raw)[idx] != 0.f;
    return ((const unsigned short*)mask_raw)[idx] != 0;
}

// ---------------------------------------------------------------------------
// Split fp32 -> bf16 hi + mid. 8 floats/thread, uint4 stores, MLP=2.
// ---------------------------------------------------------------------------
__global__ void split_bf16_kernel(const float4* __restrict__ src,
                                  uint4* __restrict__ hi,
                                  uint4* __restrict__ mid, int n8) {
    int i = blockIdx.x * blockDim.x + threadIdx.x;
    if (i >= n8) return;
    float4 a = src[2 * i];
    float4 b = src[2 * i + 1];
    __nv_bfloat162 h0, m0, h1, m1, h2, m2, h3, m3;
    split2(a.x, a.y, &h0, &m0);
    split2(a.z, a.w, &h1, &m1);
    split2(b.x, b.y, &h2, &m2);
    split2(b.z, b.w, &h3, &m3);
    uint4 H, M;
    H.x = *(uint32_t*)&h0; H.y = *(uint32_t*)&h1;
    H.z = *(uint32_t*)&h2; H.w = *(uint32_t*)&h3;
    M.x = *(uint32_t*)&m0; M.y = *(uint32_t*)&m1;
    M.z = *(uint32_t*)&m2; M.w = *(uint32_t*)&m3;
    hi[i] = H;
    mid[i] = M;
}

// ---------------------------------------------------------------------------
// TMA-fed bf16x3 GEMM (proven round 8, unchanged)
// ---------------------------------------------------------------------------
__global__ __launch_bounds__(256, 2)
void gemm_tma(const __grid_constant__ CUtensorMap tAh,
              const __grid_constant__ CUtensorMap tAm,
              const __grid_constant__ CUtensorMap tBh,
              const __grid_constant__ CUtensorMap tBm,
              const float* __restrict__ bias, float* __restrict__ C,
              int M, int Nn, int mode)
{
    extern __shared__ __align__(1024) char smem[];
    __shared__ __align__(8) uint64_t mbar[3];
    const uint32_t smb = smem_u32(smem);

    const int tid  = threadIdx.x;
    const int warp = tid >> 5;
    const int lane = tid & 31;
    const int warpM = warp & 1;
    const int warpN = warp >> 1;
    const int mBase = blockIdx.y * BM;
    const int nBase = blockIdx.x * BN;

    const int rowA = warpM * 64 + (lane & 15);
    const int xorA = (rowA & 6) << 3;
    const int colA = ((lane >> 4) * 16) ^ xorA;
    const uint32_t aOff0 = rowA * 64 + colA;
    const uint32_t aOff1 = rowA * 64 + (colA ^ 32);

    const int rowB = warpN * 32 + ((lane >> 4) << 3) + (lane & 7);
    const int xorB = (rowB & 6) << 3;
    const int colB = (((lane >> 3) & 1) * 16) ^ xorB;
    const uint32_t bOff0 = rowB * 64 + colB;
    const uint32_t bOff1 = rowB * 64 + (colB ^ 32);

    if (tid == 0) {
        mbar_init(smem_u32(&mbar[0]), 1);
        mbar_init(smem_u32(&mbar[1]), 1);
        mbar_init(smem_u32(&mbar[2]), 1);
    }
    __syncthreads();

    if (tid == 0) {
        #pragma unroll
        for (int s = 0; s < 3; s++) {
            const uint32_t mb = smem_u32(&mbar[s]);
            const uint32_t sb = smb + s * GSTAGE;
            mbar_expect(mb, GSTAGE);
            tma2d(sb,         &tAh, s * BK, mBase, mb);
            tma2d(sb +  8192, &tAm, s * BK, mBase, mb);
            tma2d(sb + 16384, &tBh, s * BK, nBase, mb);
            tma2d(sb + 24576, &tBm, s * BK, nBase, mb);
        }
    }

    float acc[4][4][4];
    #pragma unroll
    for (int i = 0; i < 4; i++)
        #pragma unroll
        for (int j = 0; j < 4; j++)
            #pragma unroll
            for (int u = 0; u < 4; u++) acc[i][j][u] = 0.f;

    int s = 0, ph = 0;
    for (int it = 0; it < NITER; it++) {
        mbar_wait(smem_u32(&mbar[s]), ph);
        const uint32_t sb = smb + s * GSTAGE;

        #pragma unroll
        for (int ks = 0; ks < 2; ks++) {
            const uint32_t aO = ks ? aOff1 : aOff0;
            const uint32_t bO = ks ? bOff1 : bOff0;
            uint32_t fBh[2][4], fBm[2][4];
            #pragma unroll
            for (int np = 0; np < 2; np++) {
                LDM4(fBh[np], sb + 16384 + bO + np * 1024);
                LDM4(fBm[np], sb + 24576 + bO + np * 1024);
            }
            #pragma unroll
            for (int mt = 0; mt < 4; mt++) {
                uint32_t fAh[4], fAm[4];
                LDM4(fAh, sb +        aO + mt * 1024);
                LDM4(fAm, sb + 8192 + aO + mt * 1024);
                #pragma unroll
                for (int nt = 0; nt < 4; nt++) {
                    const int np = nt >> 1, bi = (nt & 1) * 2;
                    MMA(acc[mt][nt], fAh, fBh[np][bi], fBh[np][bi + 1]);
                    MMA(acc[mt][nt], fAh, fBm[np][bi], fBm[np][bi + 1]);
                    MMA(acc[mt][nt], fAm, fBh[np][bi], fBh[np][bi + 1]);
                }
            }
        }
        __syncthreads();
        if (tid == 0 && it + 3 < NITER) {
            const uint32_t mb = smem_u32(&mbar[s]);
            mbar_expect(mb, GSTAGE);
            tma2d(sb,         &tAh, (it + 3) * BK, mBase, mb);
            tma2d(sb +  8192, &tAm, (it + 3) * BK, mBase, mb);
            tma2d(sb + 16384, &tBh, (it + 3) * BK, nBase, mb);
            tma2d(sb + 24576, &tBm, (it + 3) * BK, nBase, mb);
        }
        if (++s == 3) { s = 0; ph ^= 1; }
    }

    const int g = lane >> 2, tig = lane & 3;
    #pragma unroll
    for (int mt = 0; mt < 4; mt++) {
        int m0 = mBase + warpM * 64 + mt * 16 + g;
        int m1 = m0 + 8;
        int b0i = 0, n0i = 0, b1i = 0, n1i = 0;
        if (mode) {
            b0i = m0 / NN; n0i = m0 - b0i * NN;
            b1i = m1 / NN; n1i = m1 - b1i * NN;
        }
        #pragma unroll
        for (int nt = 0; nt < 4; nt++) {
            int e = nBase + warpN * 32 + nt * 8 + tig * 2;
            float bv0 = bias[e], bv1 = bias[e + 1];
            float2 r0 = make_float2(acc[mt][nt][0] + bv0, acc[mt][nt][1] + bv1);
            float2 r1 = make_float2(acc[mt][nt][2] + bv0, acc[mt][nt][3] + bv1);
            if (mode == 0) {
                if (m0 < M) *(float2*)(C + (size_t)m0 * Nn + e) = r0;
                if (m1 < M) *(float2*)(C + (size_t)m1 * Nn + e) = r1;
            } else {
                int qi = e >> 10, hh = (e >> 6) & 15, hd = e & 63;
                __nv_bfloat162 h0, mm0, h1, mm1;
                split2(r0.x, r0.y, &h0, &mm0);
                split2(r1.x, r1.y, &h1, &mm1);
                if (qi < 2) {
                    __nv_bfloat16* dh = qi ? g_kh : g_qh;
                    __nv_bfloat16* dm = qi ? g_km : g_qm;
                    if (m0 < M) {
                        size_t o = (((size_t)b0i * HH + hh) * NN + n0i) * HD + hd;
                        *(__nv_bfloat162*)(dh + o) = h0;
                        *(__nv_bfloat162*)(dm + o) = mm0;
                    }
                    if (m1 < M) {
                        size_t o = (((size_t)b1i * HH + hh) * NN + n1i) * HD + hd;
                        *(__nv_bfloat162*)(dh + o) = h1;
                        *(__nv_bfloat162*)(dm + o) = mm1;
                    }
                } else {
                    if (m0 < M) {
                        size_t o = (((size_t)b0i * HH + hh) * HD + hd) * NP + n0i;
                        g_vh[o] = h0.x;  g_vh[o + NP] = h0.y;
                        g_vm[o] = mm0.x; g_vm[o + NP] = mm0.y;
                    }
                    if (m1 < M) {
                        size_t o = (((size_t)b1i * HH + hh) * HD + hd) * NP + n1i;
                        g_vh[o] = h1.x;  g_vh[o + NP] = h1.y;
                        g_vm[o] = mm1.x; g_vm[o + NP] = mm1.y;
                    }
                }
            }
        }
    }
}

// ---------------------------------------------------------------------------
// FA2-style attention: warp owns 16 query rows x ALL 64 keys per chunk.
// P stays in registers (mma C-frag == next mma A-frag identity).
// Staged in-place K/V prefetch + exp2 softmax (both proven R14).
// ---------------------------------------------------------------------------
__global__ __launch_bounds__(256, 2)
void attn_tc(const unsigned char* __restrict__ mask_raw)
{
    extern __shared__ __align__(128) char sm[];
    const uint32_t S0 = smem_u32(sm);
    float* msk = (float*)(sm + AT_MSK);

    const int tid = threadIdx.x;
    const int warp = tid >> 5;
    const int lane = tid & 31;
    const int g = lane >> 2, tig = lane & 3;

    const int bh = blockIdx.x;
    const int b = bh >> 4, h = bh & 15;
    const int q0 = blockIdx.y * 128;

    const size_t qkbase = ((size_t)b * HH + h) * NN * HD;
    const size_t vbase0 = ((size_t)b * HH + h) * HD * NP;

    const int ldr = tid >> 2;
    const int ldc = (tid & 3) * 2;

    // ---- Q tile load ----
    {
        int r = tid >> 1;
        int cpart = (tid & 1) * 4;
        size_t off = qkbase + (size_t)(q0 + r) * HD + cpart * 8;
        uint32_t d = S0 + AT_QH + r * AT_ROWB + cpart * 16;
        #pragma unroll
        for (int u = 0; u < 4; u++) {
            cp16(d + u * 16,                    g_qh + off + u * 8, true);
            cp16(d + u * 16 + (AT_QM - AT_QH),  g_qm + off + u * 8, true);
        }
    }
    CP_COMMIT();

    // ---- K/V chunk 0 ----
    {
        size_t koff = qkbase + (size_t)ldr * HD;
        uint32_t dk = S0 + AT_KH + ldr * AT_ROWB + ldc * 16;
        size_t voff = vbase0 + (size_t)ldr * NP + ldc * 8;
        uint32_t dv = S0 + AT_VH + ldr * AT_ROWB + ldc * 16;
        #pragma unroll
        for (int u = 0; u < 2; u++) {
            cp16(dk + u * 16,                    g_kh + koff + (ldc + u) * 8, true);
            cp16(dk + u * 16 + (AT_KM - AT_KH),  g_km + koff + (ldc + u) * 8, true);
            cp16(dv + u * 16,                    g_vh + voff + u * 8, true);
            cp16(dv + u * 16 + (AT_VM - AT_VH),  g_vm + voff + u * 8, true);
        }
    }
    CP_COMMIT();

    // ---- mask (premultiplied by log2(e)) ----
    {
        const int mode = g_mask_mode;
        for (int j = tid; j < 320; j += 256) {
            float mv = -1e30f;
            if (j < NN) {
                bool mm = mask_at(mask_raw, mode, b * NN + j);
                mv = mm ? -1e30f : SH_LOG2;
            }
            msk[j] = mv;
        }
    }

    // fragment address bases
    const int aQ = (warp * 16 + (lane & 15)) * AT_ROWB + (lane >> 4) * 16;
    const int bRow = ((lane >> 4) << 3) + (lane & 7);    // within 16-row group
    const int bCol = ((lane >> 3) & 1) * 16;

    float accO[8][4];
    #pragma unroll
    for (int i = 0; i < 8; i++)
        #pragma unroll
        for (int u = 0; u < 4; u++) accO[i][u] = 0.f;
    float den0 = 0.f, den1 = 0.f;

    for (int c = 0; c < 4; c++) {
        CP_WAIT(0);
        __syncthreads();   // K(c), V(c) resident

        // ---- S = Q K^T (bf16x3); warp covers keys 0..63 ----
        float accS[8][4];
        #pragma unroll
        for (int i = 0; i < 8; i++)
            #pragma unroll
            for (int u = 0; u < 4; u++) accS[i][u] = 0.f;

        #pragma unroll
        for (int ks = 0; ks < 4; ks++) {
            uint32_t fAh[4], fAm[4];
            LDM4(fAh, S0 + AT_QH + aQ + ks * 32);
            LDM4(fAm, S0 + AT_QM + aQ + ks * 32);
            #pragma unroll
            for (int nb = 0; nb < 4; nb++) {
                const uint32_t bO = (nb * 16 + bRow) * AT_ROWB + bCol + ks * 32;
                uint32_t fBh[4], fBm[4];
                LDM4(fBh, S0 + AT_KH + bO);
                LDM4(fBm, S0 + AT_KM + bO);
                #pragma unroll
                for (int sub = 0; sub < 2; sub++) {
                    const int nb8 = nb * 2 + sub, bi = sub * 2;
                    MMA(accS[nb8], fAh, fBh[bi], fBh[bi + 1]);
                    MMA(accS[nb8], fAh, fBm[bi], fBm[bi + 1]);
                    MMA(accS[nb8], fAm, fBh[bi], fBh[bi + 1]);
                }
            }
        }
        __syncthreads();   // all warps done reading K (K buffer free)

        // ---- prefetch K(c+1) (overlaps exp + PV mma) ----
        if (c + 1 < 4) {
            size_t koff = qkbase + (size_t)((c + 1) * 64 + ldr) * HD;
            uint32_t dk = S0 + AT_KH + ldr * AT_ROWB + ldc * 16;
            #pragma unroll
            for (int u = 0; u < 2; u++) {
                cp16(dk + u * 16,                    g_kh + koff + (ldc + u) * 8, true);
                cp16(dk + u * 16 + (AT_KM - AT_KH),  g_km + koff + (ldc + u) * 8, true);
            }
            CP_COMMIT();
        }

        // ---- exp2 + in-register P pack (C-frag -> A-frag identity) ----
        uint32_t pH[4][4], pM[4][4];
        #pragma unroll
        for (int nb8 = 0; nb8 < 8; nb8++) {
            int j = c * 64 + nb8 * 8 + tig * 2;
            float mv0 = msk[j], mv1 = msk[j + 1];
            float p0 = ex2(fmaf(accS[nb8][0], SC_LOG2, mv0));
            float p1 = ex2(fmaf(accS[nb8][1], SC_LOG2, mv1));
            float p2 = ex2(fmaf(accS[nb8][2], SC_LOG2, mv0));
            float p3 = ex2(fmaf(accS[nb8][3], SC_LOG2, mv1));
            den0 += p0 + p1;
            den1 += p2 + p3;
            __nv_bfloat162 h01, m01, h23, m23;
            split2(p0, p1, &h01, &m01);
            split2(p2, p3, &h23, &m23);
            const int ks = nb8 >> 1, pos = (nb8 & 1) * 2;
            pH[ks][pos]     = *(uint32_t*)&h01;
            pH[ks][pos + 1] = *(uint32_t*)&h23;
            pM[ks][pos]     = *(uint32_t*)&m01;
            pM[ks][pos + 1] = *(uint32_t*)&m23;
        }

        // ---- O += P V (register P, bf16x3) ----
        #pragma unroll
        for (int ks = 0; ks < 4; ks++) {
            #pragma unroll
            for (int nb = 0; nb < 4; nb++) {
                const uint32_t vO = (nb * 16 + bRow) * AT_ROWB + bCol + ks * 32;
                uint32_t fVh[4], fVm[4];
                LDM4(fVh, S0 + AT_VH + vO);
                LDM4(fVm, S0 + AT_VM + vO);
                #pragma unroll
                for (int sub = 0; sub < 2; sub++) {
                    const int ob = nb * 2 + sub, bi = sub * 2;
                    MMA(accO[ob], pH[ks], fVh[bi], fVh[bi + 1]);
                    MMA(accO[ob], pH[ks], fVm[bi], fVm[bi + 1]);
                    MMA(accO[ob], pM[ks], fVh[bi], fVh[bi + 1]);
                }
            }
        }
        __syncthreads();   // all PV done (V buffer free)

        // ---- prefetch V(c+1) ----
        if (c + 1 < 4) {
            size_t voff = vbase0 + (size_t)ldr * NP + (c + 1) * 64 + ldc * 8;
            uint32_t dv = S0 + AT_VH + ldr * AT_ROWB + ldc * 16;
            #pragma unroll
            for (int u = 0; u < 2; u++) {
                cp16(dv + u * 16,                    g_vh + voff + u * 8, true);
                cp16(dv + u * 16 + (AT_VM - AT_VH),  g_vm + voff + u * 8, true);
            }
            CP_COMMIT();
        }
    }

    // ---- warp-local denominator reduce (quad lanes share a row) ----
    den0 += __shfl_xor_sync(0xffffffffu, den0, 1);
    den0 += __shfl_xor_sync(0xffffffffu, den0, 2);
    den1 += __shfl_xor_sync(0xffffffffu, den1, 1);
    den1 += __shfl_xor_sync(0xffffffffu, den1, 2);

    // ---- key 256 contribution (SIMT; fbuf overlays free P region) ----
    float* fbuf = (float*)(sm + AT_PH);
    if (tid < 64) {
        size_t ko = qkbase + (size_t)256 * HD + tid;
        fbuf[tid] = __bfloat162float(g_kh[ko]) + __bfloat162float(g_km[ko]);
        size_t vo = vbase0 + (size_t)tid * NP + 256;
        fbuf[64 + tid] = __bfloat162float(g_vh[vo]) + __bfloat162float(g_vm[vo]);
    }
    __syncthreads();
    if (tid < 128) {
        float s = 0.f;
        #pragma unroll
        for (int u = 0; u < 8; u++) {
            uint4 wh = *(uint4*)(sm + AT_QH + tid * AT_ROWB + u * 16);
            uint4 wm = *(uint4*)(sm + AT_QM + tid * AT_ROWB + u * 16);
            uint32_t hw[4] = {wh.x, wh.y, wh.z, wh.w};
            uint32_t mw[4] = {wm.x, wm.y, wm.z, wm.w};
            #pragma unroll
            for (int w2 = 0; w2 < 4; w2++) {
                float2 hf2 = __bfloat1622float2(*(__nv_bfloat162*)&hw[w2]);
                float2 mf2 = __bfloat1622float2(*(__nv_bfloat162*)&mw[w2]);
                s = fmaf(hf2.x + mf2.x, fbuf[u * 8 + w2 * 2],     s);
                s = fmaf(hf2.y + mf2.y, fbuf[u * 8 + w2 * 2 + 1], s);
            }
        }
        fbuf[128 + tid] = ex2(fmaf(s, SC_LOG2, msk[256]));
    }
    __syncthreads();

    // ---- epilogue: add key-256 term, scale, write bf16 hi/mid ----
    {
        const int rl0 = warp * 16 + g, rl1 = rl0 + 8;
        const float p0 = fbuf[128 + rl0], p1 = fbuf[128 + rl1];
        const float inv0 = 1.f / (den0 + p0);
        const float inv1 = 1.f / (den1 + p1);
        const size_t off0 = ((size_t)(b * NN + q0 + rl0)) * DD + h * 64;
        const size_t off1 = ((size_t)(b * NN + q0 + rl1)) * DD + h * 64;
        #pragma unroll
        for (int ob = 0; ob < 8; ob++) {
            int d = ob * 8 + tig * 2;
            float vA = fbuf[64 + d], vB = fbuf[64 + d + 1];
            float o0 = fmaf(p0, vA, accO[ob][0]) * inv0;
            float o1 = fmaf(p0, vB, accO[ob][1]) * inv0;
            float o2 = fmaf(p1, vA, accO[ob][2]) * inv1;
            float o3 = fmaf(p1, vB, accO[ob][3]) * inv1;
            __nv_bfloat162 hv, mv;
            split2(o0, o1, &hv, &mv);
            *(__nv_bfloat162*)(g_ah + off0 + d) = hv;
            *(__nv_bfloat162*)(g_am + off0 + d) = mv;
            split2(o2, o3, &hv, &mv);
            *(__nv_bfloat162*)(g_ah + off1 + d) = hv;
            *(__nv_bfloat162*)(g_am + off1 + d) = mv;
        }
    }
}

// ---------------------------------------------------------------------------
// Attention tail: query 256 (proven; exp2 domain, shift cancels)
// ---------------------------------------------------------------------------
__global__ __launch_bounds__(256)
void attn_tail(const unsigned char* __restrict__ mask_raw)
{
    __shared__ float q[64], pbuf[NN], accp[4][64], denp[4];
    const int tid = threadIdx.x;
    const int b = blockIdx.x >> 4, h = blockIdx.x & 15;
    const size_t qkbase = ((size_t)b * HH + h) * NN * HD;
    const size_t vbase = ((size_t)b * HH + h) * HD * NP;

    if (tid < 64) {
        size_t o = qkbase + (size_t)256 * HD + tid;
        q[tid] = __bfloat162float(g_qh[o]) + __bfloat162float(g_qm[o]);
    }
    __syncthreads();

    const int mode = g_mask_mode;
    for (int j = tid; j < NN; j += 256) {
        float p = 0.f;
        if (!mask_at(mask_raw, mode, b * NN + j)) {
            const __nv_bfloat16* kh = g_kh + qkbase + (size_t)j * HD;
            const __nv_bfloat16* km = g_km + qkbase + (size_t)j * HD;
            float s = 0.f;
            #pragma unroll
            for (int d = 0; d < 64; d++)
                s = fmaf(q[d], __bfloat162float(kh[d]) + __bfloat162float(km[d]), s);
            p = ex2(fmaf(s, SC_LOG2, SH_LOG2));
        }
        pbuf[j] = p;
    }
    __syncthreads();

    {
        int d = tid & 63, part = tid >> 6;
        int j0 = part * 64, j1 = (part == 3) ? NN : (j0 + 64);
        const __nv_bfloat16* vh = g_vh + vbase + (size_t)d * NP;
        const __nv_bfloat16* vm = g_vm + vbase + (size_t)d * NP;
        float a = 0.f, dn = 0.f;
        for (int j = j0; j < j1; j++) {
            float p = pbuf[j];
            a = fmaf(p, __bfloat162float(vh[j]) + __bfloat162float(vm[j]), a);
            dn += p;
        }
        accp[part][d] = a;
        if (d == 0) denp[part] = dn;
    }
    __syncthreads();

    if (tid < 64) {
        float o = accp[0][tid] + accp[1][tid] + accp[2][tid] + accp[3][tid];
        float den = denp[0] + denp[1] + denp[2] + denp[3];
        float val = o / den;
        __nv_bfloat16 hv = __float2bfloat16(val);
        __nv_bfloat16 mv = __float2bfloat16(val - __bfloat162float(hv));
        size_t off = ((size_t)(b * NN + 256)) * DD + h * 64 + tid;
        g_ah[off] = hv;
        g_am[off] = mv;
    }
}

// ---------------------------------------------------------------------------
// Host
// ---------------------------------------------------------------------------
typedef CUresult (*EncodeFn)(CUtensorMap*, CUtensorMapDataType, cuuint32_t, void*,
                             const cuuint64_t*, const cuuint64_t*, const cuuint32_t*,
                             const cuuint32_t*, CUtensorMapInterleave, CUtensorMapSwizzle,
                             CUtensorMapL2promotion, CUtensorMapFloatOOBfill);

static EncodeFn get_encode() {
    static EncodeFn fn = nullptr;
    if (!fn) {
        void* p = nullptr;
        cudaDriverEntryPointQueryResult qr;
        cudaGetDriverEntryPoint("cuTensorMapEncodeTiled", &p, cudaEnableDefault, &qr);
        fn = (EncodeFn)p;
    }
    return fn;
}

static void make_map(CUtensorMap* mp, void* ptr, uint64_t rows) {
    cuuint64_t dims[2] = {KDIM, rows};
    cuuint64_t strides[1] = {KDIM * 2};
    cuuint32_t box[2] = {BK, BM};
    cuuint32_t es[2] = {1, 1};
    get_encode()(mp, CU_TENSOR_MAP_DATA_TYPE_BFLOAT16, 2, ptr, dims, strides, box, es,
                 CU_TENSOR_MAP_INTERLEAVE_NONE, CU_TENSOR_MAP_SWIZZLE_64B,
                 CU_TENSOR_MAP_L2_PROMOTION_L2_128B, CU_TENSOR_MAP_FLOAT_OOB_FILL_NONE);
}

extern "C" void kernel_launch(void* const* d_in, const int* in_sizes, int n_in,
                              void* d_out, int out_size)
{
    const float* x            = (const float*)d_in[0];
    const unsigned char* mask = (const unsigned char*)d_in[1];
    const float* in_proj_w    = (const float*)d_in[2];
    const float* in_proj_b    = (const float*)d_in[3];
    const float* out_proj_w   = (const float*)d_in[4];
    const float* out_proj_b   = (const float*)d_in[5];
    float* out = (float*)d_out;

    void *xh, *xm, *ah, *am, *wh, *wm, *oh, *om;
    cudaGetSymbolAddress(&xh, g_xh);  cudaGetSymbolAddress(&xm, g_xm);
    cudaGetSymbolAddress(&ah, g_ah);  cudaGetSymbolAddress(&am, g_am);
    cudaGetSymbolAddress(&wh, g_wh);  cudaGetSymbolAddress(&wm, g_wm);
    cudaGetSymbolAddress(&oh, g_oh);  cudaGetSymbolAddress(&om, g_om);

    static bool attr_set = false;
    if (!attr_set) {
        cudaFuncSetAttribute(gemm_tma, cudaFuncAttributeMaxDynamicSharedMemorySize, GEMM_SMEM);
        cudaFuncSetAttribute(attn_tc, cudaFuncAttributeMaxDynamicSharedMemorySize, AT_SMEM);
        attr_set = true;
    }

    CUtensorMap m_xh, m_xm, m_wh, m_wm, m_ah, m_am, m_oh, m_om;
    make_map(&m_xh, xh, MROWS);
    make_map(&m_xm, xm, MROWS);
    make_map(&m_wh, wh, 3 * DD);
    make_map(&m_wm, wm, 3 * DD);
    make_map(&m_ah, ah, MROWS);
    make_map(&m_am, am, MROWS);
    make_map(&m_oh, oh, DD);
    make_map(&m_om, om, DD);

    // 1) mask dtype detection
    detect_mask_kernel<<<1, 32>>>(mask);

    // 2) split x and weights into bf16 hi/mid (8 floats/thread)
    split_bf16_kernel<<<(MROWS * DD / 8 + 255) / 256, 256>>>(
        (const float4*)x, (uint4*)xh, (uint4*)xm, MROWS * DD / 8);
    split_bf16_kernel<<<(3 * DD * DD / 8 + 255) / 256, 256>>>(
        (const float4*)in_proj_w, (uint4*)wh, (uint4*)wm, 3 * DD * DD / 8);
    split_bf16_kernel<<<(DD * DD / 8 + 255) / 256, 256>>>(
        (const float4*)out_proj_w, (uint4*)oh, (uint4*)om, DD * DD / 8);

    // 3) QKV projection (TMA-fed) -> bf16 hi/mid Q,K and transposed V
    gemm_tma<<<dim3(3 * DD / BN, (MROWS + BM - 1) / BM), 256, GEMM_SMEM>>>(
        m_xh, m_xm, m_wh, m_wm, in_proj_b, nullptr, MROWS, 3 * DD, 1);

    // 4) FA2 register-P attention + tail
    attn_tc<<<dim3(BB * HH, 2), 256, AT_SMEM>>>(mask);
    attn_tail<<<BB * HH, 256>>>(mask);

    // 5) output projection (TMA-fed) -> d_out
    gemm_tma<<<dim3(DD / BN, (MROWS + BM - 1) / BM), 256, GEMM_SMEM>>>(
        m_ah, m_am, m_oh, m_om, out_proj_b, out, MROWS, DD, 0);
}

// round 16
// speedup vs baseline: 1.0069x; 1.0069x over previous
#include <cuda_runtime.h>
#include <cuda.h>
#include <cuda_bf16.h>
#include <cstdint>
#include <math.h>

// Problem constants
#define BB   64
#define NN   257
#define DD   1024
#define HH   16
#define HD   64
#define MROWS (BB*NN)          // 16448
#define KDIM 1024
#define NP   264               // padded key stride for V^T

// exp2-domain softmax constants (uniform shift cancels in normalization)
#define SC_LOG2   0.1803368801111137f    // 0.125 * log2(e)
#define SH_LOG2  -17.312340490667562f    // -12 * log2(e)

// GEMM tiling (TMA + mma.sync bf16 path, proven round 8)
#define BM 128
#define BN 128
#define BK 32
#define NITER (KDIM/BK)        // 32
#define GSTAGE 32768
#define GEMM_SMEM (3*GSTAGE)   // 98304 -> 2 CTAs/SM

// Attention: FA2 register-P (R15) + double-buffered K/V (R10 schedule)
// smem: Q hi/mid 2x18432, two KV buffers of 36864 (KH 0, KM 9216, VH 18432,
// VM 27648 within each), mask. Total 112896 -> 2 CTAs/SM.
#define AT_ROWB 144
#define AT_QH   0
#define AT_QM   18432
#define AT_BUF0 36864
#define AT_BUFSZ 36864
#define AT_MSK  110592
#define AT_SMEM 112896

// Scratch (device globals — no allocation allowed; zero-initialized)
__device__ int g_mask_mode;
__device__ __nv_bfloat16 g_xh[(size_t)MROWS * DD], g_xm[(size_t)MROWS * DD];
__device__ __nv_bfloat16 g_ah[(size_t)MROWS * DD], g_am[(size_t)MROWS * DD];
__device__ __nv_bfloat16 g_wh[3 * DD * DD],        g_wm[3 * DD * DD];
__device__ __nv_bfloat16 g_oh[DD * DD],            g_om[DD * DD];
__device__ __nv_bfloat16 g_qh[(size_t)BB*HH*NN*HD], g_qm[(size_t)BB*HH*NN*HD];
__device__ __nv_bfloat16 g_kh[(size_t)BB*HH*NN*HD], g_km[(size_t)BB*HH*NN*HD];
__device__ __nv_bfloat16 g_vh[(size_t)BB*HH*HD*NP], g_vm[(size_t)BB*HH*HD*NP];

// ---------------------------------------------------------------------------
// PTX helpers
// ---------------------------------------------------------------------------
__device__ __forceinline__ uint32_t smem_u32(const void* p) {
    uint32_t a;
    asm("{ .reg .u64 t; cvta.to.shared.u64 t, %1; cvt.u32.u64 %0, t; }"
        : "=r"(a) : "l"(p));
    return a;
}
__device__ __forceinline__ float ex2(float x) {
    float r;
    asm("ex2.approx.f32 %0, %1;" : "=f"(r) : "f"(x));
    return r;
}
__device__ __forceinline__ void cp16(uint32_t dst, const void* src, bool pred) {
    int sz = pred ? 16 : 0;
    asm volatile("cp.async.cg.shared.global [%0], [%1], 16, %2;"
                 :: "r"(dst), "l"(src), "r"(sz));
}
#define CP_COMMIT() asm volatile("cp.async.commit_group;")
#define CP_WAIT(n)  asm volatile("cp.async.wait_group %0;" :: "n"(n))

__device__ __forceinline__ void mbar_init(uint32_t a, uint32_t cnt) {
    asm volatile("mbarrier.init.shared.b64 [%0], %1;" :: "r"(a), "r"(cnt) : "memory");
}
__device__ __forceinline__ void mbar_expect(uint32_t a, uint32_t bytes) {
    asm volatile("mbarrier.arrive.expect_tx.shared.b64 _, [%0], %1;"
                 :: "r"(a), "r"(bytes) : "memory");
}
__device__ __forceinline__ void mbar_wait(uint32_t a, uint32_t ph) {
    asm volatile(
        "{\n\t.reg .pred P;\n"
        "WLOOP%=:\n\t"
        "mbarrier.try_wait.parity.acquire.cta.shared::cta.b64 P, [%0], %1, 0x989680;\n\t"
        "@!P bra WLOOP%=;\n\t}"
        :: "r"(a), "r"(ph) : "memory");
}
__device__ __forceinline__ void tma2d(uint32_t dst, const CUtensorMap* m,
                                      int cx, int cy, uint32_t mbar) {
    asm volatile(
        "cp.async.bulk.tensor.2d.shared::cta.global.tile.mbarrier::complete_tx::bytes "
        "[%0], [%1, {%2, %3}], [%4];"
        :: "r"(dst), "l"(m), "r"(cx), "r"(cy), "r"(mbar) : "memory");
}

#define LDM4(r, addr) \
    asm volatile("ldmatrix.sync.aligned.m8n8.x4.shared.b16 {%0,%1,%2,%3}, [%4];" \
        : "=r"((r)[0]), "=r"((r)[1]), "=r"((r)[2]), "=r"((r)[3]) : "r"(addr))

#define MMA(c, a, b0, b1) \
    asm volatile("mma.sync.aligned.m16n8k16.row.col.f32.bf16.bf16.f32 " \
        "{%0,%1,%2,%3}, {%4,%5,%6,%7}, {%8,%9}, {%0,%1,%2,%3};" \
        : "+f"((c)[0]), "+f"((c)[1]), "+f"((c)[2]), "+f"((c)[3]) \
        : "r"((a)[0]), "r"((a)[1]), "r"((a)[2]), "r"((a)[3]), "r"(b0), "r"(b1))

__device__ __forceinline__ void split2(float x, float y,
                                       __nv_bfloat162* hi, __nv_bfloat162* mid) {
    __nv_bfloat162 h = __float22bfloat162_rn(make_float2(x, y));
    float2 hf = __bfloat1622float2(h);
    *hi = h;
    *mid = __float22bfloat162_rn(make_float2(x - hf.x, y - hf.y));
}

// ---------------------------------------------------------------------------
// Mask dtype detector (proven)
// ---------------------------------------------------------------------------
__global__ void detect_mask_kernel(const unsigned char* __restrict__ p) {
    if (threadIdx.x != 0 || blockIdx.x != 0) return;
    bool bf16 = false, f32 = false, u8 = false;
    for (int i = 0; i < 1024; i++) {
        unsigned char v = p[i];
        if (v == 0x3F) {
            if ((i & 3) == 1) bf16 = true; else f32 = true;
        } else if (v == 1 && (i & 3) != 0) {
            u8 = true;
        }
    }
    g_mask_mode = bf16 ? 3 : (f32 ? 2 : (u8 ? 0 : 1));
}

__device__ __forceinline__ bool mask_at(const unsigned char* mask_raw,
                                        int mode, int idx) {
    if (mode == 0) return mask_raw[idx] != 0;
    if (mode == 1) return ((const int*)mask_raw)[idx] != 0;
    if (mode == 2) return ((const float*)mask_raw)[idx] != 0.f;
    return ((const unsigned short*)mask_raw)[idx] != 0;
}

// ---------------------------------------------------------------------------
// Split fp32 -> bf16 hi + mid. 8 floats/thread, uint4 stores, MLP=2.
// ---------------------------------------------------------------------------
__global__ void split_bf16_kernel(const float4* __restrict__ src,
                                  uint4* __restrict__ hi,
                                  uint4* __restrict__ mid, int n8) {
    int i = blockIdx.x * blockDim.x + threadIdx.x;
    if (i >= n8) return;
    float4 a = src[2 * i];
    float4 b = src[2 * i + 1];
    __nv_bfloat162 h0, m0, h1, m1, h2, m2, h3, m3;
    split2(a.x, a.y, &h0, &m0);
    split2(a.z, a.w, &h1, &m1);
    split2(b.x, b.y, &h2, &m2);
    split2(b.z, b.w, &h3, &m3);
    uint4 H, M;
    H.x = *(uint32_t*)&h0; H.y = *(uint32_t*)&h1;
    H.z = *(uint32_t*)&h2; H.w = *(uint32_t*)&h3;
    M.x = *(uint32_t*)&m0; M.y = *(uint32_t*)&m1;
    M.z = *(uint32_t*)&m2; M.w = *(uint32_t*)&m3;
    hi[i] = H;
    mid[i] = M;
}

// ---------------------------------------------------------------------------
// TMA-fed bf16x3 GEMM (proven round 8, unchanged)
// ---------------------------------------------------------------------------
__global__ __launch_bounds__(256, 2)
void gemm_tma(const __grid_constant__ CUtensorMap tAh,
              const __grid_constant__ CUtensorMap tAm,
              const __grid_constant__ CUtensorMap tBh,
              const __grid_constant__ CUtensorMap tBm,
              const float* __restrict__ bias, float* __restrict__ C,
              int M, int Nn, int mode)
{
    extern __shared__ __align__(1024) char smem[];
    __shared__ __align__(8) uint64_t mbar[3];
    const uint32_t smb = smem_u32(smem);

    const int tid  = threadIdx.x;
    const int warp = tid >> 5;
    const int lane = tid & 31;
    const int warpM = warp & 1;
    const int warpN = warp >> 1;
    const int mBase = blockIdx.y * BM;
    const int nBase = blockIdx.x * BN;

    const int rowA = warpM * 64 + (lane & 15);
    const int xorA = (rowA & 6) << 3;
    const int colA = ((lane >> 4) * 16) ^ xorA;
    const uint32_t aOff0 = rowA * 64 + colA;
    const uint32_t aOff1 = rowA * 64 + (colA ^ 32);

    const int rowB = warpN * 32 + ((lane >> 4) << 3) + (lane & 7);
    const int xorB = (rowB & 6) << 3;
    const int colB = (((lane >> 3) & 1) * 16) ^ xorB;
    const uint32_t bOff0 = rowB * 64 + colB;
    const uint32_t bOff1 = rowB * 64 + (colB ^ 32);

    if (tid == 0) {
        mbar_init(smem_u32(&mbar[0]), 1);
        mbar_init(smem_u32(&mbar[1]), 1);
        mbar_init(smem_u32(&mbar[2]), 1);
    }
    __syncthreads();

    if (tid == 0) {
        #pragma unroll
        for (int s = 0; s < 3; s++) {
            const uint32_t mb = smem_u32(&mbar[s]);
            const uint32_t sb = smb + s * GSTAGE;
            mbar_expect(mb, GSTAGE);
            tma2d(sb,         &tAh, s * BK, mBase, mb);
            tma2d(sb +  8192, &tAm, s * BK, mBase, mb);
            tma2d(sb + 16384, &tBh, s * BK, nBase, mb);
            tma2d(sb + 24576, &tBm, s * BK, nBase, mb);
        }
    }

    float acc[4][4][4];
    #pragma unroll
    for (int i = 0; i < 4; i++)
        #pragma unroll
        for (int j = 0; j < 4; j++)
            #pragma unroll
            for (int u = 0; u < 4; u++) acc[i][j][u] = 0.f;

    int s = 0, ph = 0;
    for (int it = 0; it < NITER; it++) {
        mbar_wait(smem_u32(&mbar[s]), ph);
        const uint32_t sb = smb + s * GSTAGE;

        #pragma unroll
        for (int ks = 0; ks < 2; ks++) {
            const uint32_t aO = ks ? aOff1 : aOff0;
            const uint32_t bO = ks ? bOff1 : bOff0;
            uint32_t fBh[2][4], fBm[2][4];
            #pragma unroll
            for (int np = 0; np < 2; np++) {
                LDM4(fBh[np], sb + 16384 + bO + np * 1024);
                LDM4(fBm[np], sb + 24576 + bO + np * 1024);
            }
            #pragma unroll
            for (int mt = 0; mt < 4; mt++) {
                uint32_t fAh[4], fAm[4];
                LDM4(fAh, sb +        aO + mt * 1024);
                LDM4(fAm, sb + 8192 + aO + mt * 1024);
                #pragma unroll
                for (int nt = 0; nt < 4; nt++) {
                    const int np = nt >> 1, bi = (nt & 1) * 2;
                    MMA(acc[mt][nt], fAh, fBh[np][bi], fBh[np][bi + 1]);
                    MMA(acc[mt][nt], fAh, fBm[np][bi], fBm[np][bi + 1]);
                    MMA(acc[mt][nt], fAm, fBh[np][bi], fBh[np][bi + 1]);
                }
            }
        }
        __syncthreads();
        if (tid == 0 && it + 3 < NITER) {
            const uint32_t mb = smem_u32(&mbar[s]);
            mbar_expect(mb, GSTAGE);
            tma2d(sb,         &tAh, (it + 3) * BK, mBase, mb);
            tma2d(sb +  8192, &tAm, (it + 3) * BK, mBase, mb);
            tma2d(sb + 16384, &tBh, (it + 3) * BK, nBase, mb);
            tma2d(sb + 24576, &tBm, (it + 3) * BK, nBase, mb);
        }
        if (++s == 3) { s = 0; ph ^= 1; }
    }

    const int g = lane >> 2, tig = lane & 3;
    #pragma unroll
    for (int mt = 0; mt < 4; mt++) {
        int m0 = mBase + warpM * 64 + mt * 16 + g;
        int m1 = m0 + 8;
        int b0i = 0, n0i = 0, b1i = 0, n1i = 0;
        if (mode) {
            b0i = m0 / NN; n0i = m0 - b0i * NN;
            b1i = m1 / NN; n1i = m1 - b1i * NN;
        }
        #pragma unroll
        for (int nt = 0; nt < 4; nt++) {
            int e = nBase + warpN * 32 + nt * 8 + tig * 2;
            float bv0 = bias[e], bv1 = bias[e + 1];
            float2 r0 = make_float2(acc[mt][nt][0] + bv0, acc[mt][nt][1] + bv1);
            float2 r1 = make_float2(acc[mt][nt][2] + bv0, acc[mt][nt][3] + bv1);
            if (mode == 0) {
                if (m0 < M) *(float2*)(C + (size_t)m0 * Nn + e) = r0;
                if (m1 < M) *(float2*)(C + (size_t)m1 * Nn + e) = r1;
            } else {
                int qi = e >> 10, hh = (e >> 6) & 15, hd = e & 63;
                __nv_bfloat162 h0, mm0, h1, mm1;
                split2(r0.x, r0.y, &h0, &mm0);
                split2(r1.x, r1.y, &h1, &mm1);
                if (qi < 2) {
                    __nv_bfloat16* dh = qi ? g_kh : g_qh;
                    __nv_bfloat16* dm = qi ? g_km : g_qm;
                    if (m0 < M) {
                        size_t o = (((size_t)b0i * HH + hh) * NN + n0i) * HD + hd;
                        *(__nv_bfloat162*)(dh + o) = h0;
                        *(__nv_bfloat162*)(dm + o) = mm0;
                    }
                    if (m1 < M) {
                        size_t o = (((size_t)b1i * HH + hh) * NN + n1i) * HD + hd;
                        *(__nv_bfloat162*)(dh + o) = h1;
                        *(__nv_bfloat162*)(dm + o) = mm1;
                    }
                } else {
                    if (m0 < M) {
                        size_t o = (((size_t)b0i * HH + hh) * HD + hd) * NP + n0i;
                        g_vh[o] = h0.x;  g_vh[o + NP] = h0.y;
                        g_vm[o] = mm0.x; g_vm[o + NP] = mm0.y;
                    }
                    if (m1 < M) {
                        size_t o = (((size_t)b1i * HH + hh) * HD + hd) * NP + n1i;
                        g_vh[o] = h1.x;  g_vh[o + NP] = h1.y;
                        g_vm[o] = mm1.x; g_vm[o + NP] = mm1.y;
                    }
                }
            }
        }
    }
}

// ---------------------------------------------------------------------------
// FA2 register-P attention (R15 body) + double-buffered K/V (R10 schedule)
// at 2 CTAs/SM. Within-buffer: KH +0, KM +9216, VH +18432, VM +27648.
// ---------------------------------------------------------------------------
__device__ __forceinline__ void attn_load_chunk(
    uint32_t bufbase, int ci, size_t qkbase, size_t vbase0, int ldr, int ldc)
{
    size_t koff = qkbase + (size_t)(ci * 64 + ldr) * HD;
    uint32_t dk = bufbase + ldr * AT_ROWB + ldc * 16;
    size_t voff = vbase0 + (size_t)ldr * NP + ci * 64 + ldc * 8;
    uint32_t dv = bufbase + 18432 + ldr * AT_ROWB + ldc * 16;
    #pragma unroll
    for (int u = 0; u < 2; u++) {
        cp16(dk + u * 16,        g_kh + koff + (ldc + u) * 8, true);
        cp16(dk + u * 16 + 9216, g_km + koff + (ldc + u) * 8, true);
        cp16(dv + u * 16,        g_vh + voff + u * 8, true);
        cp16(dv + u * 16 + 9216, g_vm + voff + u * 8, true);
    }
}

__global__ __launch_bounds__(256, 2)
void attn_tc(const unsigned char* __restrict__ mask_raw)
{
    extern __shared__ __align__(128) char sm[];
    const uint32_t S0 = smem_u32(sm);
    float* msk = (float*)(sm + AT_MSK);

    const int tid = threadIdx.x;
    const int warp = tid >> 5;
    const int lane = tid & 31;
    const int g = lane >> 2, tig = lane & 3;

    const int bh = blockIdx.x;
    const int b = bh >> 4, h = bh & 15;
    const int q0 = blockIdx.y * 128;

    const size_t qkbase = ((size_t)b * HH + h) * NN * HD;
    const size_t vbase0 = ((size_t)b * HH + h) * HD * NP;

    const int ldr = tid >> 2;
    const int ldc = (tid & 3) * 2;

    // ---- Q tile + K/V chunk 0 (one group), then chunk 1 (second group) ----
    {
        int r = tid >> 1;
        int cpart = (tid & 1) * 4;
        size_t off = qkbase + (size_t)(q0 + r) * HD + cpart * 8;
        uint32_t d = S0 + AT_QH + r * AT_ROWB + cpart * 16;
        #pragma unroll
        for (int u = 0; u < 4; u++) {
            cp16(d + u * 16,                    g_qh + off + u * 8, true);
            cp16(d + u * 16 + (AT_QM - AT_QH),  g_qm + off + u * 8, true);
        }
    }
    attn_load_chunk(S0 + AT_BUF0, 0, qkbase, vbase0, ldr, ldc);
    CP_COMMIT();                                      // group: {Q, chunk0}
    attn_load_chunk(S0 + AT_BUF0 + AT_BUFSZ, 1, qkbase, vbase0, ldr, ldc);
    CP_COMMIT();                                      // group: {chunk1}

    // ---- mask (premultiplied by log2(e)) ----
    {
        const int mode = g_mask_mode;
        for (int j = tid; j < 320; j += 256) {
            float mv = -1e30f;
            if (j < NN) {
                bool mm = mask_at(mask_raw, mode, b * NN + j);
                mv = mm ? -1e30f : SH_LOG2;
            }
            msk[j] = mv;
        }
    }

    // fragment address bases
    const int aQ = (warp * 16 + (lane & 15)) * AT_ROWB + (lane >> 4) * 16;
    const int bRow = ((lane >> 4) << 3) + (lane & 7);
    const int bCol = ((lane >> 3) & 1) * 16;

    float accO[8][4];
    #pragma unroll
    for (int i = 0; i < 8; i++)
        #pragma unroll
        for (int u = 0; u < 4; u++) accO[i][u] = 0.f;
    float den0 = 0.f, den1 = 0.f;

    for (int c = 0; c < 4; c++) {
        if (c < 3) { CP_WAIT(1); } else { CP_WAIT(0); }
        __syncthreads();                 // chunk c resident in buf(c&1)
        const uint32_t bufK = S0 + AT_BUF0 + (c & 1) * AT_BUFSZ;
        const uint32_t bufV = bufK + 18432;

        // ---- S = Q K^T (bf16x3) ----
        float accS[8][4];
        #pragma unroll
        for (int i = 0; i < 8; i++)
            #pragma unroll
            for (int u = 0; u < 4; u++) accS[i][u] = 0.f;

        #pragma unroll
        for (int ks = 0; ks < 4; ks++) {
            uint32_t fAh[4], fAm[4];
            LDM4(fAh, S0 + AT_QH + aQ + ks * 32);
            LDM4(fAm, S0 + AT_QM + aQ + ks * 32);
            #pragma unroll
            for (int nb = 0; nb < 4; nb++) {
                const uint32_t bO = (nb * 16 + bRow) * AT_ROWB + bCol + ks * 32;
                uint32_t fBh[4], fBm[4];
                LDM4(fBh, bufK + bO);
                LDM4(fBm, bufK + 9216 + bO);
                #pragma unroll
                for (int sub = 0; sub < 2; sub++) {
                    const int nb8 = nb * 2 + sub, bi = sub * 2;
                    MMA(accS[nb8], fAh, fBh[bi], fBh[bi + 1]);
                    MMA(accS[nb8], fAh, fBm[bi], fBm[bi + 1]);
                    MMA(accS[nb8], fAm, fBh[bi], fBh[bi + 1]);
                }
            }
        }

        // ---- exp2 + in-register P pack (C-frag -> A-frag identity) ----
        uint32_t pH[4][4], pM[4][4];
        #pragma unroll
        for (int nb8 = 0; nb8 < 8; nb8++) {
            int j = c * 64 + nb8 * 8 + tig * 2;
            float mv0 = msk[j], mv1 = msk[j + 1];
            float p0 = ex2(fmaf(accS[nb8][0], SC_LOG2, mv0));
            float p1 = ex2(fmaf(accS[nb8][1], SC_LOG2, mv1));
            float p2 = ex2(fmaf(accS[nb8][2], SC_LOG2, mv0));
            float p3 = ex2(fmaf(accS[nb8][3], SC_LOG2, mv1));
            den0 += p0 + p1;
            den1 += p2 + p3;
            __nv_bfloat162 h01, m01, h23, m23;
            split2(p0, p1, &h01, &m01);
            split2(p2, p3, &h23, &m23);
            const int ks = nb8 >> 1, pos = (nb8 & 1) * 2;
            pH[ks][pos]     = *(uint32_t*)&h01;
            pH[ks][pos + 1] = *(uint32_t*)&h23;
            pM[ks][pos]     = *(uint32_t*)&m01;
            pM[ks][pos + 1] = *(uint32_t*)&m23;
        }

        // ---- O += P V (register P, bf16x3) ----
        #pragma unroll
        for (int ks = 0; ks < 4; ks++) {
            #pragma unroll
            for (int nb = 0; nb < 4; nb++) {
                const uint32_t vO = (nb * 16 + bRow) * AT_ROWB + bCol + ks * 32;
                uint32_t fVh[4], fVm[4];
                LDM4(fVh, bufV + vO);
                LDM4(fVm, bufV + 9216 + vO);
                #pragma unroll
                for (int sub = 0; sub < 2; sub++) {
                    const int ob = nb * 2 + sub, bi = sub * 2;
                    MMA(accO[ob], pH[ks], fVh[bi], fVh[bi + 1]);
                    MMA(accO[ob], pH[ks], fVm[bi], fVm[bi + 1]);
                    MMA(accO[ob], pM[ks], fVh[bi], fVh[bi + 1]);
                }
            }
        }
        __syncthreads();                 // buf(c&1) fully consumed

        // ---- refill buf(c&1) with chunk c+2 (overlaps chunk c+1 compute) ----
        if (c + 2 < 4) {
            attn_load_chunk(bufK, c + 2, qkbase, vbase0, ldr, ldc);
            CP_COMMIT();
        }
    }

    // ---- warp-local denominator reduce (quad lanes share a row) ----
    den0 += __shfl_xor_sync(0xffffffffu, den0, 1);
    den0 += __shfl_xor_sync(0xffffffffu, den0, 2);
    den1 += __shfl_xor_sync(0xffffffffu, den1, 1);
    den1 += __shfl_xor_sync(0xffffffffu, den1, 2);

    // ---- key 256 contribution (SIMT; fbuf overlays dead KV buffers) ----
    float* fbuf = (float*)(sm + AT_BUF0);
    if (tid < 64) {
        size_t ko = qkbase + (size_t)256 * HD + tid;
        fbuf[tid] = __bfloat162float(g_kh[ko]) + __bfloat162float(g_km[ko]);
        size_t vo = vbase0 + (size_t)tid * NP + 256;
        fbuf[64 + tid] = __bfloat162float(g_vh[vo]) + __bfloat162float(g_vm[vo]);
    }
    __syncthreads();
    if (tid < 128) {
        float s = 0.f;
        #pragma unroll
        for (int u = 0; u < 8; u++) {
            uint4 wh = *(uint4*)(sm + AT_QH + tid * AT_ROWB + u * 16);
            uint4 wm = *(uint4*)(sm + AT_QM + tid * AT_ROWB + u * 16);
            uint32_t hw[4] = {wh.x, wh.y, wh.z, wh.w};
            uint32_t mw[4] = {wm.x, wm.y, wm.z, wm.w};
            #pragma unroll
            for (int w2 = 0; w2 < 4; w2++) {
                float2 hf2 = __bfloat1622float2(*(__nv_bfloat162*)&hw[w2]);
                float2 mf2 = __bfloat1622float2(*(__nv_bfloat162*)&mw[w2]);
                s = fmaf(hf2.x + mf2.x, fbuf[u * 8 + w2 * 2],     s);
                s = fmaf(hf2.y + mf2.y, fbuf[u * 8 + w2 * 2 + 1], s);
            }
        }
        fbuf[128 + tid] = ex2(fmaf(s, SC_LOG2, msk[256]));
    }
    __syncthreads();

    // ---- epilogue: add key-256 term, scale, write bf16 hi/mid ----
    {
        const int rl0 = warp * 16 + g, rl1 = rl0 + 8;
        const float p0 = fbuf[128 + rl0], p1 = fbuf[128 + rl1];
        const float inv0 = 1.f / (den0 + p0);
        const float inv1 = 1.f / (den1 + p1);
        const size_t off0 = ((size_t)(b * NN + q0 + rl0)) * DD + h * 64;
        const size_t off1 = ((size_t)(b * NN + q0 + rl1)) * DD + h * 64;
        #pragma unroll
        for (int ob = 0; ob < 8; ob++) {
            int d = ob * 8 + tig * 2;
            float vA = fbuf[64 + d], vB = fbuf[64 + d + 1];
            float o0 = fmaf(p0, vA, accO[ob][0]) * inv0;
            float o1 = fmaf(p0, vB, accO[ob][1]) * inv0;
            float o2 = fmaf(p1, vA, accO[ob][2]) * inv1;
            float o3 = fmaf(p1, vB, accO[ob][3]) * inv1;
            __nv_bfloat162 hv, mv;
            split2(o0, o1, &hv, &mv);
            *(__nv_bfloat162*)(g_ah + off0 + d) = hv;
            *(__nv_bfloat162*)(g_am + off0 + d) = mv;
            split2(o2, o3, &hv, &mv);
            *(__nv_bfloat162*)(g_ah + off1 + d) = hv;
            *(__nv_bfloat162*)(g_am + off1 + d) = mv;
        }
    }
}

// ---------------------------------------------------------------------------
// Attention tail: query 256 (proven; exp2 domain, shift cancels)
// ---------------------------------------------------------------------------
__global__ __launch_bounds__(256)
void attn_tail(const unsigned char* __restrict__ mask_raw)
{
    __shared__ float q[64], pbuf[NN], accp[4][64], denp[4];
    const int tid = threadIdx.x;
    const int b = blockIdx.x >> 4, h = blockIdx.x & 15;
    const size_t qkbase = ((size_t)b * HH + h) * NN * HD;
    const size_t vbase = ((size_t)b * HH + h) * HD * NP;

    if (tid < 64) {
        size_t o = qkbase + (size_t)256 * HD + tid;
        q[tid] = __bfloat162float(g_qh[o]) + __bfloat162float(g_qm[o]);
    }
    __syncthreads();

    const int mode = g_mask_mode;
    for (int j = tid; j < NN; j += 256) {
        float p = 0.f;
        if (!mask_at(mask_raw, mode, b * NN + j)) {
            const __nv_bfloat16* kh = g_kh + qkbase + (size_t)j * HD;
            const __nv_bfloat16* km = g_km + qkbase + (size_t)j * HD;
            float s = 0.f;
            #pragma unroll
            for (int d = 0; d < 64; d++)
                s = fmaf(q[d], __bfloat162float(kh[d]) + __bfloat162float(km[d]), s);
            p = ex2(fmaf(s, SC_LOG2, SH_LOG2));
        }
        pbuf[j] = p;
    }
    __syncthreads();

    {
        int d = tid & 63, part = tid >> 6;
        int j0 = part * 64, j1 = (part == 3) ? NN : (j0 + 64);
        const __nv_bfloat16* vh = g_vh + vbase + (size_t)d * NP;
        const __nv_bfloat16* vm = g_vm + vbase + (size_t)d * NP;
        float a = 0.f, dn = 0.f;
        for (int j = j0; j < j1; j++) {
            float p = pbuf[j];
            a = fmaf(p, __bfloat162float(vh[j]) + __bfloat162float(vm[j]), a);
            dn += p;
        }
        accp[part][d] = a;
        if (d == 0) denp[part] = dn;
    }
    __syncthreads();

    if (tid < 64) {
        float o = accp[0][tid] + accp[1][tid] + accp[2][tid] + accp[3][tid];
        float den = denp[0] + denp[1] + denp[2] + denp[3];
        float val = o / den;
        __nv_bfloat16 hv = __float2bfloat16(val);
        __nv_bfloat16 mv = __float2bfloat16(val - __bfloat162float(hv));
        size_t off = ((size_t)(b * NN + 256)) * DD + h * 64 + tid;
        g_ah[off] = hv;
        g_am[off] = mv;
    }
}

// ---------------------------------------------------------------------------
// Host
// ---------------------------------------------------------------------------
typedef CUresult (*EncodeFn)(CUtensorMap*, CUtensorMapDataType, cuuint32_t, void*,
                             const cuuint64_t*, const cuuint64_t*, const cuuint32_t*,
                             const cuuint32_t*, CUtensorMapInterleave, CUtensorMapSwizzle,
                             CUtensorMapL2promotion, CUtensorMapFloatOOBfill);

static EncodeFn get_encode() {
    static EncodeFn fn = nullptr;
    if (!fn) {
        void* p = nullptr;
        cudaDriverEntryPointQueryResult qr;
        cudaGetDriverEntryPoint("cuTensorMapEncodeTiled", &p, cudaEnableDefault, &qr);
        fn = (EncodeFn)p;
    }
    return fn;
}

static void make_map(CUtensorMap* mp, void* ptr, uint64_t rows) {
    cuuint64_t dims[2] = {KDIM, rows};
    cuuint64_t strides[1] = {KDIM * 2};
    cuuint32_t box[2] = {BK, BM};
    cuuint32_t es[2] = {1, 1};
    get_encode()(mp, CU_TENSOR_MAP_DATA_TYPE_BFLOAT16, 2, ptr, dims, strides, box, es,
                 CU_TENSOR_MAP_INTERLEAVE_NONE, CU_TENSOR_MAP_SWIZZLE_64B,
                 CU_TENSOR_MAP_L2_PROMOTION_L2_128B, CU_TENSOR_MAP_FLOAT_OOB_FILL_NONE);
}

extern "C" void kernel_launch(void* const* d_in, const int* in_sizes, int n_in,
                              void* d_out, int out_size)
{
    const float* x            = (const float*)d_in[0];
    const unsigned char* mask = (const unsigned char*)d_in[1];
    const float* in_proj_w    = (const float*)d_in[2];
    const float* in_proj_b    = (const float*)d_in[3];
    const float* out_proj_w   = (const float*)d_in[4];
    const float* out_proj_b   = (const float*)d_in[5];
    float* out = (float*)d_out;

    void *xh, *xm, *ah, *am, *wh, *wm, *oh, *om;
    cudaGetSymbolAddress(&xh, g_xh);  cudaGetSymbolAddress(&xm, g_xm);
    cudaGetSymbolAddress(&ah, g_ah);  cudaGetSymbolAddress(&am, g_am);
    cudaGetSymbolAddress(&wh, g_wh);  cudaGetSymbolAddress(&wm, g_wm);
    cudaGetSymbolAddress(&oh, g_oh);  cudaGetSymbolAddress(&om, g_om);

    static bool attr_set = false;
    if (!attr_set) {
        cudaFuncSetAttribute(gemm_tma, cudaFuncAttributeMaxDynamicSharedMemorySize, GEMM_SMEM);
        cudaFuncSetAttribute(attn_tc, cudaFuncAttributeMaxDynamicSharedMemorySize, AT_SMEM);
        attr_set = true;
    }

    CUtensorMap m_xh, m_xm, m_wh, m_wm, m_ah, m_am, m_oh, m_om;
    make_map(&m_xh, xh, MROWS);
    make_map(&m_xm, xm, MROWS);
    make_map(&m_wh, wh, 3 * DD);
    make_map(&m_wm, wm, 3 * DD);
    make_map(&m_ah, ah, MROWS);
    make_map(&m_am, am, MROWS);
    make_map(&m_oh, oh, DD);
    make_map(&m_om, om, DD);

    // 1) mask dtype detection
    detect_mask_kernel<<<1, 32>>>(mask);

    // 2) split x and weights into bf16 hi/mid (8 floats/thread)
    split_bf16_kernel<<<(MROWS * DD / 8 + 255) / 256, 256>>>(
        (const float4*)x, (uint4*)xh, (uint4*)xm, MROWS * DD / 8);
    split_bf16_kernel<<<(3 * DD * DD / 8 + 255) / 256, 256>>>(
        (const float4*)in_proj_w, (uint4*)wh, (uint4*)wm, 3 * DD * DD / 8);
    split_bf16_kernel<<<(DD * DD / 8 + 255) / 256, 256>>>(
        (const float4*)out_proj_w, (uint4*)oh, (uint4*)om, DD * DD / 8);

    // 3) QKV projection (TMA-fed) -> bf16 hi/mid Q,K and transposed V
    gemm_tma<<<dim3(3 * DD / BN, (MROWS + BM - 1) / BM), 256, GEMM_SMEM>>>(
        m_xh, m_xm, m_wh, m_wm, in_proj_b, nullptr, MROWS, 3 * DD, 1);

    // 4) FA2 register-P attention (double-buffered K/V, 2 CTAs/SM) + tail
    attn_tc<<<dim3(BB * HH, 2), 256, AT_SMEM>>>(mask);
    attn_tail<<<BB * HH, 256>>>(mask);

    // 5) output projection (TMA-fed) -> d_out
    gemm_tma<<<dim3(DD / BN, (MROWS + BM - 1) / BM), 256, GEMM_SMEM>>>(
        m_ah, m_am, m_oh, m_om, out_proj_b, out, MROWS, DD, 0);
}